// round 13
// baseline (speedup 1.0000x reference)
#include <cuda_runtime.h>
#include <cuda_fp16.h>
#include <cstdint>
#include <math.h>

#define N_ENTITY 64368
#define N_REL 40
#define DIM 128
#define NUM_BASES 8
#define N_EDGES 1200000
#define BATCH 64
#define MAX_SEED 32

#define SCAN_T 1024
#define SCAN_NBLK 63          // 63*1024 = 64512 >= N_ENTITY
#define TN 64
#define NBLK ((N_ENTITY + TN - 1) / TN)   // 1006 score blocks
#define UPAD (BATCH + 4)
#define NPAD (TN + 4)

// ---------------- device scratch (static: no allocations allowed) ----------
__device__ __half g_W[(size_t)N_EDGES * DIM];            // 307 MB compact fp16 rows
__device__ float  g_nodes[(size_t)N_ENTITY * DIM];       // 33 MB
__device__ float  g_u[BATCH * DIM];
__device__ int    g_mask_is_int32;
__device__ unsigned long long g_relmask[N_ENTITY];       // bit r set if (r,src) used
__device__ int    g_cnt[N_ENTITY];
__device__ unsigned long long g_scantmp[N_ENTITY];       // packed block-local excl scan
__device__ int    g_off[N_ENTITY + 1];
__device__ int    g_cur[N_ENTITY];
__device__ int    g_pairbase[N_ENTITY];                  // excl prefix of popc(relmask)
__device__ unsigned long long g_blocksum[SCAN_NBLK];
__device__ int    g_eidx[N_EDGES];                       // W slot index, grouped by dst
__device__ float  g_pmax[BATCH * NBLK];
__device__ float  g_psum[BATCH * NBLK];

// ---------------- zero relmask + dst counts; last block detects mask dtype --
__global__ void zero_aux_kernel(const unsigned char* mask) {
    if (blockIdx.x == gridDim.x - 1) {
        __shared__ int s_flag;
        if (threadIdx.x == 0) s_flag = 0;
        __syncthreads();
        for (int i = threadIdx.x; i < BATCH * MAX_SEED; i += blockDim.x) {
            if ((i & 3) != 0 && mask[i] != 0) atomicOr(&s_flag, 1);
        }
        __syncthreads();
        if (threadIdx.x == 0) g_mask_is_int32 = (s_flag == 0) ? 1 : 0;
        return;
    }
    int i = blockIdx.x * blockDim.x + threadIdx.x;
    if (i < N_ENTITY) {
        g_relmask[i] = 0ull;
        g_cnt[i] = 0;
    }
}

// ---------------- build per-src used-relation bitmask + dst histogram -------
__global__ void edge_pass1_kernel(const int* __restrict__ ei, const int* __restrict__ et) {
    int i = blockIdx.x * blockDim.x + threadIdx.x;
    if (i >= N_EDGES) return;
    int src = __ldg(ei + i);
    int dst = __ldg(ei + N_EDGES + i);
    int rel = __ldg(et + i);
    atomicOr(&g_relmask[src], 1ull << rel);
    atomicAdd(&g_cnt[dst], 1);
}

// ---------------- packed dual scan: low32 = dst counts, high32 = pair counts
__global__ void scanA_kernel() {
    __shared__ unsigned long long s[SCAN_T];
    int t = threadIdx.x;
    int idx = blockIdx.x * SCAN_T + t;
    unsigned long long v = 0ull;
    if (idx < N_ENTITY)
        v = (unsigned long long)g_cnt[idx]
          | ((unsigned long long)__popcll(g_relmask[idx]) << 32);
    s[t] = v;
    __syncthreads();
    for (int o = 1; o < SCAN_T; o <<= 1) {
        unsigned long long x = (t >= o) ? s[t - o] : 0ull;
        __syncthreads();
        s[t] += x;
        __syncthreads();
    }
    if (idx < N_ENTITY) g_scantmp[idx] = s[t] - v;   // block-local exclusive
    if (t == SCAN_T - 1) g_blocksum[blockIdx.x] = s[t];
}

__global__ void scanC_kernel() {
    __shared__ unsigned long long s[64];
    int t = threadIdx.x;
    if (t < 64) s[t] = (t < SCAN_NBLK) ? g_blocksum[t] : 0ull;
    __syncthreads();
    for (int o = 1; o < 64; o <<= 1) {
        unsigned long long x = (t >= o && t < 64) ? s[t - o] : 0ull;
        __syncthreads();
        if (t < 64) s[t] += x;
        __syncthreads();
    }
    unsigned long long base = (blockIdx.x == 0) ? 0ull : s[blockIdx.x - 1];
    int idx = blockIdx.x * SCAN_T + t;
    if (idx < N_ENTITY) {
        unsigned long long v = g_scantmp[idx] + base;
        int off = (int)(v & 0xffffffffull);
        g_off[idx] = off;
        g_cur[idx] = off;
        g_pairbase[idx] = (int)(v >> 32);
    }
    if (idx == 0) g_off[N_ENTITY] = N_EDGES;
}

// ---------------- scatter: edge -> dst bucket, payload = compact W slot -----
__global__ void scatter_kernel(const int* __restrict__ ei, const int* __restrict__ et) {
    int i = blockIdx.x * blockDim.x + threadIdx.x;
    if (i >= N_EDGES) return;
    int src = __ldg(ei + i);
    int dst = __ldg(ei + N_EDGES + i);
    int rel = __ldg(et + i);
    unsigned long long mm = __ldg(&g_relmask[src]);
    int slot = __ldg(&g_pairbase[src]) + __popcll(mm & ((1ull << rel) - 1ull));
    int p = atomicAdd(&g_cur[dst], 1);
    g_eidx[p] = slot;
}

// ---------------- W rows: dense per used (rel,src) pair, FFMA2 --------------
__global__ void w_kernel(const float* __restrict__ basis, const float* __restrict__ att) {
    __shared__ unsigned long long s_att2[N_REL * NUM_BASES];   // (c,c) packed
    for (int i = threadIdx.x; i < N_REL * NUM_BASES; i += blockDim.x) {
        float c = att[i];
        unsigned long long p;
        asm("mov.b64 %0, {%1, %1};" : "=l"(p) : "f"(c));
        s_att2[i] = p;
    }
    __syncthreads();

    int warp = threadIdx.x >> 5;
    int lane = threadIdx.x & 31;
    int n = blockIdx.x * (blockDim.x >> 5) + warp;
    if (n >= N_ENTITY) return;

    unsigned long long m = g_relmask[n];
    if (m == 0ull) return;

    unsigned long long bas2[NUM_BASES * 2];
#pragma unroll
    for (int b = 0; b < NUM_BASES; b++) {
        ulonglong2 v = *(const ulonglong2*)(basis + ((size_t)b * N_ENTITY + n) * DIM + lane * 4);
        bas2[2 * b] = v.x;
        bas2[2 * b + 1] = v.y;
    }

    uint2* wp = ((uint2*)g_W) + (size_t)g_pairbase[n] * 32 + lane;

    while (m) {
        int r = __ffsll((long long)m) - 1;
        m &= m - 1;
        unsigned long long a01 = 0ull, a23 = 0ull;
#pragma unroll
        for (int b = 0; b < NUM_BASES; b++) {
            unsigned long long c2 = s_att2[r * NUM_BASES + b];
            asm("fma.rn.f32x2 %0, %1, %2, %0;" : "+l"(a01) : "l"(bas2[2 * b]), "l"(c2));
            asm("fma.rn.f32x2 %0, %1, %2, %0;" : "+l"(a23) : "l"(bas2[2 * b + 1]), "l"(c2));
        }
        float x, y, z, w;
        asm("mov.b64 {%0, %1}, %2;" : "=f"(x), "=f"(y) : "l"(a01));
        asm("mov.b64 {%0, %1}, %2;" : "=f"(z), "=f"(w) : "l"(a23));
        __half2 h01 = __floats2half2_rn(x, y);
        __half2 h23 = __floats2half2_rn(z, w);
        *wp = make_uint2(*(unsigned*)&h01, *(unsigned*)&h23);
        wp += 32;
    }
}

// ---------------- segment aggregation: one warp per dst ---------------------
__device__ __forceinline__ void acc_row(float4& a, int slot, int lane) {
    uint2 pk = __ldg(((const uint2*)g_W) + (size_t)slot * 32 + lane);
    float2 f01 = __half22float2(*(__half2*)&pk.x);
    float2 f23 = __half22float2(*(__half2*)&pk.y);
    a.x += f01.x; a.y += f01.y; a.z += f23.x; a.w += f23.y;
}

__global__ void agg_kernel(const float* __restrict__ root, const float* __restrict__ bias) {
    int dst = blockIdx.x * (blockDim.x >> 5) + (threadIdx.x >> 5);
    if (dst >= N_ENTITY) return;
    int lane = threadIdx.x & 31;

    float4 acc = ((const float4*)root)[(size_t)dst * 32 + lane];
    float4 bb = ((const float4*)bias)[lane];
    acc.x += bb.x; acc.y += bb.y; acc.z += bb.z; acc.w += bb.w;

    int i = __ldg(&g_off[dst]);
    int end = __ldg(&g_off[dst + 1]);

    for (; i + 8 <= end; i += 8) {
        int e0 = __ldg(&g_eidx[i]);
        int e1 = __ldg(&g_eidx[i + 1]);
        int e2 = __ldg(&g_eidx[i + 2]);
        int e3 = __ldg(&g_eidx[i + 3]);
        int e4 = __ldg(&g_eidx[i + 4]);
        int e5 = __ldg(&g_eidx[i + 5]);
        int e6 = __ldg(&g_eidx[i + 6]);
        int e7 = __ldg(&g_eidx[i + 7]);
        acc_row(acc, e0, lane); acc_row(acc, e1, lane);
        acc_row(acc, e2, lane); acc_row(acc, e3, lane);
        acc_row(acc, e4, lane); acc_row(acc, e5, lane);
        acc_row(acc, e6, lane); acc_row(acc, e7, lane);
    }
    for (; i + 4 <= end; i += 4) {
        int e0 = __ldg(&g_eidx[i]);
        int e1 = __ldg(&g_eidx[i + 1]);
        int e2 = __ldg(&g_eidx[i + 2]);
        int e3 = __ldg(&g_eidx[i + 3]);
        acc_row(acc, e0, lane); acc_row(acc, e1, lane);
        acc_row(acc, e2, lane); acc_row(acc, e3, lane);
    }
    for (; i < end; i++) acc_row(acc, __ldg(&g_eidx[i]), lane);

    ((float4*)g_nodes)[(size_t)dst * 32 + lane] = acc;
}

// ---------------- attention pooling over seed sets --------------------------
__global__ void pool_kernel(const int* __restrict__ seed_idx,
                            const void* __restrict__ seed_mask,
                            const float* __restrict__ attn_a,
                            const float* __restrict__ attn_b) {
    int b = blockIdx.x;
    int tid = threadIdx.x;
    int lane = tid & 31;
    int warp = tid >> 5;

    __shared__ float s_h[MAX_SEED][DIM];
    __shared__ float s_e[MAX_SEED];
    __shared__ float s_attn[MAX_SEED];
    __shared__ int   s_idx[MAX_SEED];
    __shared__ unsigned char s_mask[MAX_SEED];

    if (tid < MAX_SEED) {
        s_idx[tid] = seed_idx[b * MAX_SEED + tid];
        int mk;
        if (g_mask_is_int32)
            mk = (((const int*)seed_mask)[b * MAX_SEED + tid] != 0);
        else
            mk = (((const unsigned char*)seed_mask)[b * MAX_SEED + tid] != 0);
        s_mask[tid] = (unsigned char)mk;
    }
    __syncthreads();

    for (int l = 0; l < MAX_SEED; l++)
        s_h[l][tid] = g_nodes[(size_t)s_idx[l] * DIM + tid];
    __syncthreads();

#pragma unroll
    for (int i = 0; i < 8; i++) {
        int l = warp * 8 + i;
        float part = 0.f;
#pragma unroll
        for (int jj = 0; jj < 4; jj++) {
            int j = lane + 32 * jj;
            float m = 0.f;
#pragma unroll 8
            for (int k = 0; k < DIM; k++)
                m += s_h[l][k] * __ldg(attn_a + (size_t)k * DIM + j);
            part += tanhf(m) * __ldg(attn_b + j);
        }
#pragma unroll
        for (int o = 16; o > 0; o >>= 1) part += __shfl_xor_sync(0xffffffffu, part, o);
        if (lane == 0) s_e[l] = part;
    }
    __syncthreads();

    if (warp == 0) {
        float e = s_mask[lane] ? s_e[lane] : -INFINITY;
        float mx = e;
#pragma unroll
        for (int o = 16; o > 0; o >>= 1) mx = fmaxf(mx, __shfl_xor_sync(0xffffffffu, mx, o));
        float p = s_mask[lane] ? __expf(e - mx) : 0.f;
        float sm = p;
#pragma unroll
        for (int o = 16; o > 0; o >>= 1) sm += __shfl_xor_sync(0xffffffffu, sm, o);
        s_attn[lane] = p / sm;
    }
    __syncthreads();

    float u = 0.f;
#pragma unroll
    for (int l = 0; l < MAX_SEED; l++) u += s_attn[l] * s_h[l][tid];
    g_u[b * DIM + tid] = u;
}

// ---------------- scores = u @ nodes^T + bias, fused lse partials -----------
// s_u2: duplicated (u,u) 64-bit pairs so the FFMA2 mainloop needs no packing.
__global__ void scores_kernel(const float* __restrict__ output_bias,
                              float* __restrict__ out) {
    extern __shared__ char smem[];
    unsigned long long* s_u2 = (unsigned long long*)smem;         // [DIM][UPAD] pairs
    float* s_nT = (float*)(smem + (size_t)DIM * UPAD * 8);        // [DIM][NPAD]

    int tid = threadIdx.x;
    int blk = blockIdx.x;
    int n0 = blk * TN;

    for (int i = tid; i < BATCH * DIM; i += 256) {
        int bb = i >> 7, d = i & 127;
        float v = g_u[i];
        unsigned long long p;
        asm("mov.b64 %0, {%1, %1};" : "=l"(p) : "f"(v));
        s_u2[d * UPAD + bb] = p;
    }
    for (int i = tid; i < TN * DIM; i += 256) {
        int nn = i >> 7, d = i & 127;
        int n = n0 + nn;
        s_nT[d * NPAD + nn] = (n < N_ENTITY) ? g_nodes[(size_t)n * DIM + d] : 0.f;
    }
    __syncthreads();

    int tb = tid >> 4;    // 4 batch rows each
    int tn = tid & 15;    // 4 nodes each
    unsigned long long acc2[4][2];
#pragma unroll
    for (int ii = 0; ii < 4; ii++) { acc2[ii][0] = 0ull; acc2[ii][1] = 0ull; }

#pragma unroll 4
    for (int k = 0; k < DIM; k++) {
        ulonglong2 up0 = *(const ulonglong2*)&s_u2[k * UPAD + 4 * tb];
        ulonglong2 up1 = *(const ulonglong2*)&s_u2[k * UPAD + 4 * tb + 2];
        ulonglong2 np = *(const ulonglong2*)&s_nT[k * NPAD + 4 * tn];  // (n0,n1),(n2,n3)
        asm("fma.rn.f32x2 %0, %1, %2, %0;" : "+l"(acc2[0][0]) : "l"(np.x), "l"(up0.x));
        asm("fma.rn.f32x2 %0, %1, %2, %0;" : "+l"(acc2[0][1]) : "l"(np.y), "l"(up0.x));
        asm("fma.rn.f32x2 %0, %1, %2, %0;" : "+l"(acc2[1][0]) : "l"(np.x), "l"(up0.y));
        asm("fma.rn.f32x2 %0, %1, %2, %0;" : "+l"(acc2[1][1]) : "l"(np.y), "l"(up0.y));
        asm("fma.rn.f32x2 %0, %1, %2, %0;" : "+l"(acc2[2][0]) : "l"(np.x), "l"(up1.x));
        asm("fma.rn.f32x2 %0, %1, %2, %0;" : "+l"(acc2[2][1]) : "l"(np.y), "l"(up1.x));
        asm("fma.rn.f32x2 %0, %1, %2, %0;" : "+l"(acc2[3][0]) : "l"(np.x), "l"(up1.y));
        asm("fma.rn.f32x2 %0, %1, %2, %0;" : "+l"(acc2[3][1]) : "l"(np.y), "l"(up1.y));
    }

    float acc[4][4];
#pragma unroll
    for (int ii = 0; ii < 4; ii++) {
        asm("mov.b64 {%0, %1}, %2;" : "=f"(acc[ii][0]), "=f"(acc[ii][1]) : "l"(acc2[ii][0]));
        asm("mov.b64 {%0, %1}, %2;" : "=f"(acc[ii][2]), "=f"(acc[ii][3]) : "l"(acc2[ii][1]));
    }

#pragma unroll
    for (int ii = 0; ii < 4; ii++) {
        int bb = 4 * tb + ii;
        // finalize values, store, and fold into per-row lse partials
        float v[4];
        float mloc = -1e30f;
#pragma unroll
        for (int jj = 0; jj < 4; jj++) {
            int n = n0 + 4 * tn + jj;
            if (n < N_ENTITY) {
                v[jj] = acc[ii][jj] + __ldg(&output_bias[n]);
                out[(size_t)bb * N_ENTITY + n] = v[jj];
                mloc = fmaxf(mloc, v[jj]);
            } else {
                v[jj] = -1e30f;
            }
        }
        // reduce max over the 16 tn lanes (offsets 1..8 stay inside the group)
        float m = mloc;
#pragma unroll
        for (int o = 8; o > 0; o >>= 1) m = fmaxf(m, __shfl_xor_sync(0xffffffffu, m, o));
        float sloc = 0.f;
#pragma unroll
        for (int jj = 0; jj < 4; jj++) {
            int n = n0 + 4 * tn + jj;
            if (n < N_ENTITY) sloc += __expf(v[jj] - m);
        }
#pragma unroll
        for (int o = 8; o > 0; o >>= 1) sloc += __shfl_xor_sync(0xffffffffu, sloc, o);
        if (tn == 0) {
            g_pmax[(size_t)bb * NBLK + blk] = m;
            g_psum[(size_t)bb * NBLK + blk] = sloc;
        }
    }
}

// ---------------- merge lse partials + CE mean: one block, 1024 threads -----
__global__ void lse_merge_kernel(const float* __restrict__ scores,
                                 const int* __restrict__ labels,
                                 float* __restrict__ out) {
    __shared__ float s_loss[BATCH];
    int warp = threadIdx.x >> 5;
    int lane = threadIdx.x & 31;

    for (int b = warp; b < BATCH; b += 32) {
        float M = -1e30f;
        for (int i = lane; i < NBLK; i += 32) M = fmaxf(M, g_pmax[(size_t)b * NBLK + i]);
#pragma unroll
        for (int o = 16; o > 0; o >>= 1) M = fmaxf(M, __shfl_xor_sync(0xffffffffu, M, o));
        float S = 0.f;
        for (int i = lane; i < NBLK; i += 32)
            S += g_psum[(size_t)b * NBLK + i] * __expf(g_pmax[(size_t)b * NBLK + i] - M);
#pragma unroll
        for (int o = 16; o > 0; o >>= 1) S += __shfl_xor_sync(0xffffffffu, S, o);
        if (lane == 0)
            s_loss[b] = (logf(S) + M) - scores[(size_t)b * N_ENTITY + labels[b]];
    }
    __syncthreads();
    if (threadIdx.x < 32) {
        float v = s_loss[threadIdx.x] + s_loss[threadIdx.x + 32];
#pragma unroll
        for (int o = 16; o > 0; o >>= 1) v += __shfl_xor_sync(0xffffffffu, v, o);
        if (threadIdx.x == 0) out[(size_t)BATCH * N_ENTITY] = v / (float)BATCH;
    }
}

// ---------------- launch ----------------------------------------------------
extern "C" void kernel_launch(void* const* d_in, const int* in_sizes, int n_in,
                              void* d_out, int out_size) {
    const float* basis       = (const float*)d_in[0];
    const float* att         = (const float*)d_in[1];
    const float* root        = (const float*)d_in[2];
    const float* rgcn_bias   = (const float*)d_in[3];
    const float* attn_a      = (const float*)d_in[4];
    const float* attn_b      = (const float*)d_in[5];
    const float* output_bias = (const float*)d_in[6];
    const int*   edge_index  = (const int*)d_in[7];
    const int*   edge_type   = (const int*)d_in[8];
    const int*   seed_idx    = (const int*)d_in[9];
    const void*  seed_mask   = d_in[10];
    const int*   labels      = (const int*)d_in[11];
    float* out = (float*)d_out;

    const int scores_smem = (int)((size_t)DIM * UPAD * 8 + (size_t)DIM * NPAD * 4);  // 104448
    static int smem_set = 0;
    if (!smem_set) {
        cudaFuncSetAttribute(scores_kernel, cudaFuncAttributeMaxDynamicSharedMemorySize,
                             scores_smem);
        smem_set = 1;
    }

    zero_aux_kernel<<<(N_ENTITY + 255) / 256 + 1, 256>>>((const unsigned char*)seed_mask);
    edge_pass1_kernel<<<(N_EDGES + 255) / 256, 256>>>(edge_index, edge_type);
    scanA_kernel<<<SCAN_NBLK, SCAN_T>>>();
    scanC_kernel<<<SCAN_NBLK, SCAN_T>>>();
    scatter_kernel<<<(N_EDGES + 255) / 256, 256>>>(edge_index, edge_type);
    w_kernel<<<(N_ENTITY + 7) / 8, 256>>>(basis, att);
    agg_kernel<<<(N_ENTITY + 7) / 8, 256>>>(root, rgcn_bias);
    pool_kernel<<<BATCH, 128>>>(seed_idx, seed_mask, attn_a, attn_b);
    scores_kernel<<<NBLK, 256, scores_smem>>>(output_bias, out);
    lse_merge_kernel<<<1, 1024>>>(out, labels, out);
}

// round 14
// speedup vs baseline: 1.0749x; 1.0749x over previous
#include <cuda_runtime.h>
#include <cuda_fp16.h>
#include <cstdint>
#include <math.h>

#define N_ENTITY 64368
#define N_REL 40
#define DIM 128
#define NUM_BASES 8
#define N_EDGES 1200000
#define BATCH 64
#define MAX_SEED 32

#define SCAN_T 1024
#define SCAN_NBLK 63          // 63*1024 = 64512 >= N_ENTITY
#define LSE_SEG 12            // 64368 / 12 = 5364, divisible by 4 (float4-aligned)
#define SEG_LEN (N_ENTITY / LSE_SEG)

// ---------------- device scratch (static: no allocations allowed) ----------
__device__ __half g_W[(size_t)N_EDGES * DIM];            // 307 MB compact fp16 rows
__device__ float  g_nodes[(size_t)N_ENTITY * DIM];       // 33 MB
__device__ float  g_u[BATCH * DIM];
__device__ int    g_mask_is_int32;
__device__ unsigned long long g_relmask[N_ENTITY];       // bit r set if (r,src) used
__device__ int    g_cnt[N_ENTITY];
__device__ unsigned long long g_scantmp[N_ENTITY];       // packed block-local excl scan
__device__ int    g_off[N_ENTITY + 1];
__device__ int    g_cur[N_ENTITY];
__device__ int    g_pairbase[N_ENTITY];                  // excl prefix of popc(relmask)
__device__ unsigned long long g_blocksum[SCAN_NBLK];
__device__ int    g_eidx[N_EDGES];                       // W slot index, grouped by dst
__device__ float  g_pmax[BATCH * LSE_SEG];
__device__ float  g_psum[BATCH * LSE_SEG];

// ---------------- zero relmask + dst counts; last block detects mask dtype --
__global__ void zero_aux_kernel(const unsigned char* mask) {
    if (blockIdx.x == gridDim.x - 1) {
        __shared__ int s_flag;
        if (threadIdx.x == 0) s_flag = 0;
        __syncthreads();
        for (int i = threadIdx.x; i < BATCH * MAX_SEED; i += blockDim.x) {
            if ((i & 3) != 0 && mask[i] != 0) atomicOr(&s_flag, 1);
        }
        __syncthreads();
        if (threadIdx.x == 0) g_mask_is_int32 = (s_flag == 0) ? 1 : 0;
        return;
    }
    int i = blockIdx.x * blockDim.x + threadIdx.x;
    if (i < N_ENTITY) {
        g_relmask[i] = 0ull;
        g_cnt[i] = 0;
    }
}

// ---------------- build per-src used-relation bitmask + dst histogram -------
__global__ void edge_pass1_kernel(const int* __restrict__ ei, const int* __restrict__ et) {
    int i = blockIdx.x * blockDim.x + threadIdx.x;
    if (i >= N_EDGES) return;
    int src = __ldg(ei + i);
    int dst = __ldg(ei + N_EDGES + i);
    int rel = __ldg(et + i);
    atomicOr(&g_relmask[src], 1ull << rel);
    atomicAdd(&g_cnt[dst], 1);
}

// ---------------- packed dual scan: low32 = dst counts, high32 = pair counts
__global__ void scanA_kernel() {
    __shared__ unsigned long long s[SCAN_T];
    int t = threadIdx.x;
    int idx = blockIdx.x * SCAN_T + t;
    unsigned long long v = 0ull;
    if (idx < N_ENTITY)
        v = (unsigned long long)g_cnt[idx]
          | ((unsigned long long)__popcll(g_relmask[idx]) << 32);
    s[t] = v;
    __syncthreads();
    for (int o = 1; o < SCAN_T; o <<= 1) {
        unsigned long long x = (t >= o) ? s[t - o] : 0ull;
        __syncthreads();
        s[t] += x;
        __syncthreads();
    }
    if (idx < N_ENTITY) g_scantmp[idx] = s[t] - v;   // block-local exclusive
    if (t == SCAN_T - 1) g_blocksum[blockIdx.x] = s[t];
}

__global__ void scanC_kernel() {
    __shared__ unsigned long long s[64];
    int t = threadIdx.x;
    if (t < 64) s[t] = (t < SCAN_NBLK) ? g_blocksum[t] : 0ull;
    __syncthreads();
    for (int o = 1; o < 64; o <<= 1) {
        unsigned long long x = (t >= o && t < 64) ? s[t - o] : 0ull;
        __syncthreads();
        if (t < 64) s[t] += x;
        __syncthreads();
    }
    unsigned long long base = (blockIdx.x == 0) ? 0ull : s[blockIdx.x - 1];
    int idx = blockIdx.x * SCAN_T + t;
    if (idx < N_ENTITY) {
        unsigned long long v = g_scantmp[idx] + base;
        int off = (int)(v & 0xffffffffull);
        g_off[idx] = off;
        g_cur[idx] = off;
        g_pairbase[idx] = (int)(v >> 32);
    }
    if (idx == 0) g_off[N_ENTITY] = N_EDGES;
}

// ---------------- scatter: edge -> dst bucket, payload = compact W slot -----
__global__ void scatter_kernel(const int* __restrict__ ei, const int* __restrict__ et) {
    int i = blockIdx.x * blockDim.x + threadIdx.x;
    if (i >= N_EDGES) return;
    int src = __ldg(ei + i);
    int dst = __ldg(ei + N_EDGES + i);
    int rel = __ldg(et + i);
    unsigned long long mm = __ldg(&g_relmask[src]);
    int slot = __ldg(&g_pairbase[src]) + __popcll(mm & ((1ull << rel) - 1ull));
    int p = atomicAdd(&g_cur[dst], 1);
    g_eidx[p] = slot;
}

// ---------------- W rows: dense per used (rel,src) pair, FFMA2 --------------
__global__ void w_kernel(const float* __restrict__ basis, const float* __restrict__ att) {
    __shared__ unsigned long long s_att2[N_REL * NUM_BASES];   // (c,c) packed
    for (int i = threadIdx.x; i < N_REL * NUM_BASES; i += blockDim.x) {
        float c = att[i];
        unsigned long long p;
        asm("mov.b64 %0, {%1, %1};" : "=l"(p) : "f"(c));
        s_att2[i] = p;
    }
    __syncthreads();

    int warp = threadIdx.x >> 5;
    int lane = threadIdx.x & 31;
    int n = blockIdx.x * (blockDim.x >> 5) + warp;
    if (n >= N_ENTITY) return;

    unsigned long long m = g_relmask[n];
    if (m == 0ull) return;

    unsigned long long bas2[NUM_BASES * 2];
#pragma unroll
    for (int b = 0; b < NUM_BASES; b++) {
        ulonglong2 v = *(const ulonglong2*)(basis + ((size_t)b * N_ENTITY + n) * DIM + lane * 4);
        bas2[2 * b] = v.x;
        bas2[2 * b + 1] = v.y;
    }

    uint2* wp = ((uint2*)g_W) + (size_t)g_pairbase[n] * 32 + lane;

    while (m) {
        int r = __ffsll((long long)m) - 1;
        m &= m - 1;
        unsigned long long a01 = 0ull, a23 = 0ull;
#pragma unroll
        for (int b = 0; b < NUM_BASES; b++) {
            unsigned long long c2 = s_att2[r * NUM_BASES + b];
            asm("fma.rn.f32x2 %0, %1, %2, %0;" : "+l"(a01) : "l"(bas2[2 * b]), "l"(c2));
            asm("fma.rn.f32x2 %0, %1, %2, %0;" : "+l"(a23) : "l"(bas2[2 * b + 1]), "l"(c2));
        }
        float x, y, z, w;
        asm("mov.b64 {%0, %1}, %2;" : "=f"(x), "=f"(y) : "l"(a01));
        asm("mov.b64 {%0, %1}, %2;" : "=f"(z), "=f"(w) : "l"(a23));
        __half2 h01 = __floats2half2_rn(x, y);
        __half2 h23 = __floats2half2_rn(z, w);
        *wp = make_uint2(*(unsigned*)&h01, *(unsigned*)&h23);
        wp += 32;
    }
}

// ---------------- segment aggregation: one warp per dst ---------------------
__device__ __forceinline__ void acc_row(float4& a, int slot, int lane) {
    uint2 pk = __ldg(((const uint2*)g_W) + (size_t)slot * 32 + lane);
    float2 f01 = __half22float2(*(__half2*)&pk.x);
    float2 f23 = __half22float2(*(__half2*)&pk.y);
    a.x += f01.x; a.y += f01.y; a.z += f23.x; a.w += f23.y;
}

__global__ void agg_kernel(const float* __restrict__ root, const float* __restrict__ bias) {
    int dst = blockIdx.x * (blockDim.x >> 5) + (threadIdx.x >> 5);
    if (dst >= N_ENTITY) return;
    int lane = threadIdx.x & 31;

    float4 acc = ((const float4*)root)[(size_t)dst * 32 + lane];
    float4 bb = ((const float4*)bias)[lane];
    acc.x += bb.x; acc.y += bb.y; acc.z += bb.z; acc.w += bb.w;

    int i = __ldg(&g_off[dst]);
    int end = __ldg(&g_off[dst + 1]);

    for (; i + 8 <= end; i += 8) {
        int e0 = __ldg(&g_eidx[i]);
        int e1 = __ldg(&g_eidx[i + 1]);
        int e2 = __ldg(&g_eidx[i + 2]);
        int e3 = __ldg(&g_eidx[i + 3]);
        int e4 = __ldg(&g_eidx[i + 4]);
        int e5 = __ldg(&g_eidx[i + 5]);
        int e6 = __ldg(&g_eidx[i + 6]);
        int e7 = __ldg(&g_eidx[i + 7]);
        acc_row(acc, e0, lane); acc_row(acc, e1, lane);
        acc_row(acc, e2, lane); acc_row(acc, e3, lane);
        acc_row(acc, e4, lane); acc_row(acc, e5, lane);
        acc_row(acc, e6, lane); acc_row(acc, e7, lane);
    }
    for (; i + 4 <= end; i += 4) {
        int e0 = __ldg(&g_eidx[i]);
        int e1 = __ldg(&g_eidx[i + 1]);
        int e2 = __ldg(&g_eidx[i + 2]);
        int e3 = __ldg(&g_eidx[i + 3]);
        acc_row(acc, e0, lane); acc_row(acc, e1, lane);
        acc_row(acc, e2, lane); acc_row(acc, e3, lane);
    }
    for (; i < end; i++) acc_row(acc, __ldg(&g_eidx[i]), lane);

    ((float4*)g_nodes)[(size_t)dst * 32 + lane] = acc;
}

// ---------------- attention pooling over seed sets --------------------------
__global__ void pool_kernel(const int* __restrict__ seed_idx,
                            const void* __restrict__ seed_mask,
                            const float* __restrict__ attn_a,
                            const float* __restrict__ attn_b) {
    int b = blockIdx.x;
    int tid = threadIdx.x;
    int lane = tid & 31;
    int warp = tid >> 5;

    __shared__ float s_h[MAX_SEED][DIM];
    __shared__ float s_e[MAX_SEED];
    __shared__ float s_attn[MAX_SEED];
    __shared__ int   s_idx[MAX_SEED];
    __shared__ unsigned char s_mask[MAX_SEED];

    if (tid < MAX_SEED) {
        s_idx[tid] = seed_idx[b * MAX_SEED + tid];
        int mk;
        if (g_mask_is_int32)
            mk = (((const int*)seed_mask)[b * MAX_SEED + tid] != 0);
        else
            mk = (((const unsigned char*)seed_mask)[b * MAX_SEED + tid] != 0);
        s_mask[tid] = (unsigned char)mk;
    }
    __syncthreads();

    for (int l = 0; l < MAX_SEED; l++)
        s_h[l][tid] = g_nodes[(size_t)s_idx[l] * DIM + tid];
    __syncthreads();

#pragma unroll
    for (int i = 0; i < 8; i++) {
        int l = warp * 8 + i;
        float part = 0.f;
#pragma unroll
        for (int jj = 0; jj < 4; jj++) {
            int j = lane + 32 * jj;
            float m = 0.f;
#pragma unroll 8
            for (int k = 0; k < DIM; k++)
                m += s_h[l][k] * __ldg(attn_a + (size_t)k * DIM + j);
            part += tanhf(m) * __ldg(attn_b + j);
        }
#pragma unroll
        for (int o = 16; o > 0; o >>= 1) part += __shfl_xor_sync(0xffffffffu, part, o);
        if (lane == 0) s_e[l] = part;
    }
    __syncthreads();

    if (warp == 0) {
        float e = s_mask[lane] ? s_e[lane] : -INFINITY;
        float mx = e;
#pragma unroll
        for (int o = 16; o > 0; o >>= 1) mx = fmaxf(mx, __shfl_xor_sync(0xffffffffu, mx, o));
        float p = s_mask[lane] ? __expf(e - mx) : 0.f;
        float sm = p;
#pragma unroll
        for (int o = 16; o > 0; o >>= 1) sm += __shfl_xor_sync(0xffffffffu, sm, o);
        s_attn[lane] = p / sm;
    }
    __syncthreads();

    float u = 0.f;
#pragma unroll
    for (int l = 0; l < MAX_SEED; l++) u += s_attn[l] * s_h[l][tid];
    g_u[b * DIM + tid] = u;
}

// ---------------- scores = u @ nodes^T + output_bias (FFMA2, R11 smem) ------
#define TN 64
#define UPAD (BATCH + 4)
#define NPAD (TN + 4)
__global__ void scores_kernel(const float* __restrict__ output_bias,
                              float* __restrict__ out) {
    extern __shared__ float smem[];
    float* s_uT = smem;                    // [DIM][UPAD]
    float* s_nT = smem + DIM * UPAD;       // [DIM][NPAD]

    int tid = threadIdx.x;
    int n0 = blockIdx.x * TN;

    for (int i = tid; i < BATCH * DIM; i += 256) {
        int bb = i >> 7, d = i & 127;
        s_uT[d * UPAD + bb] = g_u[i];
    }
    for (int i = tid; i < TN * DIM; i += 256) {
        int nn = i >> 7, d = i & 127;
        int n = n0 + nn;
        s_nT[d * NPAD + nn] = (n < N_ENTITY) ? g_nodes[(size_t)n * DIM + d] : 0.f;
    }
    __syncthreads();

    int tb = tid >> 4;    // 4 batch rows each
    int tn = tid & 15;    // 4 nodes each
    unsigned long long acc2[4][2];
#pragma unroll
    for (int ii = 0; ii < 4; ii++) { acc2[ii][0] = 0ull; acc2[ii][1] = 0ull; }

#pragma unroll 4
    for (int k = 0; k < DIM; k++) {
        float4 ua = *(const float4*)&s_uT[k * UPAD + 4 * tb];
        ulonglong2 np = *(const ulonglong2*)&s_nT[k * NPAD + 4 * tn];  // (n0,n1),(n2,n3)
        unsigned long long u0, u1, u2, u3;
        asm("mov.b64 %0, {%1, %1};" : "=l"(u0) : "f"(ua.x));
        asm("mov.b64 %0, {%1, %1};" : "=l"(u1) : "f"(ua.y));
        asm("mov.b64 %0, {%1, %1};" : "=l"(u2) : "f"(ua.z));
        asm("mov.b64 %0, {%1, %1};" : "=l"(u3) : "f"(ua.w));
        asm("fma.rn.f32x2 %0, %1, %2, %0;" : "+l"(acc2[0][0]) : "l"(np.x), "l"(u0));
        asm("fma.rn.f32x2 %0, %1, %2, %0;" : "+l"(acc2[0][1]) : "l"(np.y), "l"(u0));
        asm("fma.rn.f32x2 %0, %1, %2, %0;" : "+l"(acc2[1][0]) : "l"(np.x), "l"(u1));
        asm("fma.rn.f32x2 %0, %1, %2, %0;" : "+l"(acc2[1][1]) : "l"(np.y), "l"(u1));
        asm("fma.rn.f32x2 %0, %1, %2, %0;" : "+l"(acc2[2][0]) : "l"(np.x), "l"(u2));
        asm("fma.rn.f32x2 %0, %1, %2, %0;" : "+l"(acc2[2][1]) : "l"(np.y), "l"(u2));
        asm("fma.rn.f32x2 %0, %1, %2, %0;" : "+l"(acc2[3][0]) : "l"(np.x), "l"(u3));
        asm("fma.rn.f32x2 %0, %1, %2, %0;" : "+l"(acc2[3][1]) : "l"(np.y), "l"(u3));
    }

    float acc[4][4];
#pragma unroll
    for (int ii = 0; ii < 4; ii++) {
        asm("mov.b64 {%0, %1}, %2;" : "=f"(acc[ii][0]), "=f"(acc[ii][1]) : "l"(acc2[ii][0]));
        asm("mov.b64 {%0, %1}, %2;" : "=f"(acc[ii][2]), "=f"(acc[ii][3]) : "l"(acc2[ii][1]));
    }

#pragma unroll
    for (int ii = 0; ii < 4; ii++) {
        int bb = 4 * tb + ii;
#pragma unroll
        for (int jj = 0; jj < 4; jj++) {
            int n = n0 + 4 * tn + jj;
            if (n < N_ENTITY)
                out[(size_t)bb * N_ENTITY + n] = acc[ii][jj] + output_bias[n];
        }
    }
}

// ---------------- segmented logsumexp: grid (BATCH, LSE_SEG), float4 --------
__global__ void lse_part_kernel(const float* __restrict__ scores) {
    int b = blockIdx.x;
    int s = blockIdx.y;
    int tid = threadIdx.x;
    const float4* row = (const float4*)(scores + (size_t)b * N_ENTITY + s * SEG_LEN);
    const int n4 = SEG_LEN / 4;   // 1341
    __shared__ float s_red[256];

    float mx = -1e30f;
    for (int i = tid; i < n4; i += 256) {
        float4 v = row[i];
        mx = fmaxf(mx, fmaxf(fmaxf(v.x, v.y), fmaxf(v.z, v.w)));
    }
    s_red[tid] = mx;
    __syncthreads();
    for (int o = 128; o > 0; o >>= 1) {
        if (tid < o) s_red[tid] = fmaxf(s_red[tid], s_red[tid + o]);
        __syncthreads();
    }
    float rmax = s_red[0];
    __syncthreads();

    float sum = 0.f;
    for (int i = tid; i < n4; i += 256) {
        float4 v = row[i];
        sum += __expf(v.x - rmax) + __expf(v.y - rmax) + __expf(v.z - rmax) + __expf(v.w - rmax);
    }
    s_red[tid] = sum;
    __syncthreads();
    for (int o = 128; o > 0; o >>= 1) {
        if (tid < o) s_red[tid] += s_red[tid + o];
        __syncthreads();
    }
    if (tid == 0) {
        g_pmax[b * LSE_SEG + s] = rmax;
        g_psum[b * LSE_SEG + s] = s_red[0];
    }
}

// merge partials + CE mean; one block of BATCH threads
__global__ void lse_final_kernel(const float* __restrict__ scores,
                                 const int* __restrict__ labels,
                                 float* __restrict__ out) {
    __shared__ float s[BATCH];
    int t = threadIdx.x;   // = batch row
    float M = -1e30f;
#pragma unroll
    for (int j = 0; j < LSE_SEG; j++) M = fmaxf(M, g_pmax[t * LSE_SEG + j]);
    float S = 0.f;
#pragma unroll
    for (int j = 0; j < LSE_SEG; j++)
        S += g_psum[t * LSE_SEG + j] * __expf(g_pmax[t * LSE_SEG + j] - M);
    s[t] = (logf(S) + M) - scores[(size_t)t * N_ENTITY + labels[t]];
    __syncthreads();
    for (int o = 32; o > 0; o >>= 1) {
        if (t < o) s[t] += s[t + o];
        __syncthreads();
    }
    if (t == 0) out[(size_t)BATCH * N_ENTITY] = s[0] / (float)BATCH;
}

// ---------------- launch ----------------------------------------------------
extern "C" void kernel_launch(void* const* d_in, const int* in_sizes, int n_in,
                              void* d_out, int out_size) {
    const float* basis       = (const float*)d_in[0];
    const float* att         = (const float*)d_in[1];
    const float* root        = (const float*)d_in[2];
    const float* rgcn_bias   = (const float*)d_in[3];
    const float* attn_a      = (const float*)d_in[4];
    const float* attn_b      = (const float*)d_in[5];
    const float* output_bias = (const float*)d_in[6];
    const int*   edge_index  = (const int*)d_in[7];
    const int*   edge_type   = (const int*)d_in[8];
    const int*   seed_idx    = (const int*)d_in[9];
    const void*  seed_mask   = d_in[10];
    const int*   labels      = (const int*)d_in[11];
    float* out = (float*)d_out;

    const int scores_smem = (int)((DIM * UPAD + DIM * NPAD) * sizeof(float));   // 69632
    static int smem_set = 0;
    if (!smem_set) {
        cudaFuncSetAttribute(scores_kernel, cudaFuncAttributeMaxDynamicSharedMemorySize,
                             scores_smem);
        smem_set = 1;
    }

    zero_aux_kernel<<<(N_ENTITY + 255) / 256 + 1, 256>>>((const unsigned char*)seed_mask);
    edge_pass1_kernel<<<(N_EDGES + 255) / 256, 256>>>(edge_index, edge_type);
    scanA_kernel<<<SCAN_NBLK, SCAN_T>>>();
    scanC_kernel<<<SCAN_NBLK, SCAN_T>>>();
    scatter_kernel<<<(N_EDGES + 255) / 256, 256>>>(edge_index, edge_type);
    w_kernel<<<(N_ENTITY + 7) / 8, 256>>>(basis, att);
    agg_kernel<<<(N_ENTITY + 7) / 8, 256>>>(root, rgcn_bias);
    pool_kernel<<<BATCH, 128>>>(seed_idx, seed_mask, attn_a, attn_b);
    scores_kernel<<<(N_ENTITY + TN - 1) / TN, 256, scores_smem>>>(output_bias, out);
    lse_part_kernel<<<dim3(BATCH, LSE_SEG), 256>>>(out);
    lse_final_kernel<<<1, BATCH>>>(out, labels, out);
}

// round 15
// speedup vs baseline: 1.0958x; 1.0195x over previous
#include <cuda_runtime.h>
#include <cuda_fp16.h>
#include <cstdint>
#include <math.h>

#define N_ENTITY 64368
#define N_REL 40
#define DIM 128
#define NUM_BASES 8
#define N_EDGES 1200000
#define BATCH 64
#define MAX_SEED 32

#define SCAN_T 1024
#define SCAN_NBLK 63          // 63*1024 = 64512 >= N_ENTITY
#define LSE_SEG 12            // 64368 / 12 = 5364, divisible by 4 (float4-aligned)
#define SEG_LEN (N_ENTITY / LSE_SEG)

// ---------------- device scratch (static: no allocations allowed) ----------
__device__ __half g_W[(size_t)N_EDGES * DIM];            // 307 MB compact fp16 rows
__device__ float  g_nodes[(size_t)N_ENTITY * DIM];       // 33 MB
__device__ float  g_u[BATCH * DIM];
__device__ int    g_mask_is_int32;
__device__ unsigned long long g_relmask[N_ENTITY];       // bit r set if (r,src) used
__device__ int    g_cnt[N_ENTITY];
__device__ unsigned long long g_scantmp[N_ENTITY];       // packed block-local excl scan
__device__ int    g_off[N_ENTITY + 1];
__device__ int    g_cur[N_ENTITY];
__device__ int    g_pairbase[N_ENTITY];                  // excl prefix of popc(relmask)
__device__ unsigned long long g_blocksum[SCAN_NBLK];
__device__ int    g_eidx[N_EDGES];                       // W slot index, grouped by dst
__device__ float  g_pmax[BATCH * LSE_SEG];
__device__ float  g_psum[BATCH * LSE_SEG];

// ---------------- zero relmask + dst counts; last block detects mask dtype --
__global__ void zero_aux_kernel(const unsigned char* mask) {
    if (blockIdx.x == gridDim.x - 1) {
        __shared__ int s_flag;
        if (threadIdx.x == 0) s_flag = 0;
        __syncthreads();
        for (int i = threadIdx.x; i < BATCH * MAX_SEED; i += blockDim.x) {
            if ((i & 3) != 0 && mask[i] != 0) atomicOr(&s_flag, 1);
        }
        __syncthreads();
        if (threadIdx.x == 0) g_mask_is_int32 = (s_flag == 0) ? 1 : 0;
        return;
    }
    int i = blockIdx.x * blockDim.x + threadIdx.x;
    if (i < N_ENTITY) {
        g_relmask[i] = 0ull;
        g_cnt[i] = 0;
    }
}

// ---------------- build per-src used-relation bitmask + dst histogram -------
__global__ void edge_pass1_kernel(const int* __restrict__ ei, const int* __restrict__ et) {
    int i = blockIdx.x * blockDim.x + threadIdx.x;
    if (i >= N_EDGES) return;
    int src = __ldg(ei + i);
    int dst = __ldg(ei + N_EDGES + i);
    int rel = __ldg(et + i);
    atomicOr(&g_relmask[src], 1ull << rel);
    atomicAdd(&g_cnt[dst], 1);
}

// ---------------- packed dual scan: low32 = dst counts, high32 = pair counts
__global__ void scanA_kernel() {
    __shared__ unsigned long long s[SCAN_T];
    int t = threadIdx.x;
    int idx = blockIdx.x * SCAN_T + t;
    unsigned long long v = 0ull;
    if (idx < N_ENTITY)
        v = (unsigned long long)g_cnt[idx]
          | ((unsigned long long)__popcll(g_relmask[idx]) << 32);
    s[t] = v;
    __syncthreads();
    for (int o = 1; o < SCAN_T; o <<= 1) {
        unsigned long long x = (t >= o) ? s[t - o] : 0ull;
        __syncthreads();
        s[t] += x;
        __syncthreads();
    }
    if (idx < N_ENTITY) g_scantmp[idx] = s[t] - v;   // block-local exclusive
    if (t == SCAN_T - 1) g_blocksum[blockIdx.x] = s[t];
}

__global__ void scanC_kernel() {
    __shared__ unsigned long long s[64];
    int t = threadIdx.x;
    if (t < 64) s[t] = (t < SCAN_NBLK) ? g_blocksum[t] : 0ull;
    __syncthreads();
    for (int o = 1; o < 64; o <<= 1) {
        unsigned long long x = (t >= o && t < 64) ? s[t - o] : 0ull;
        __syncthreads();
        if (t < 64) s[t] += x;
        __syncthreads();
    }
    unsigned long long base = (blockIdx.x == 0) ? 0ull : s[blockIdx.x - 1];
    int idx = blockIdx.x * SCAN_T + t;
    if (idx < N_ENTITY) {
        unsigned long long v = g_scantmp[idx] + base;
        int off = (int)(v & 0xffffffffull);
        g_off[idx] = off;
        g_cur[idx] = off;
        g_pairbase[idx] = (int)(v >> 32);
    }
    if (idx == 0) g_off[N_ENTITY] = N_EDGES;
}

// ---------------- scatter: edge -> dst bucket, payload = compact W slot -----
// Triggers programmatic launch completion FIRST: the following w_kernel (PDL)
// is fully independent of everything this kernel writes.
__global__ void scatter_kernel(const int* __restrict__ ei, const int* __restrict__ et) {
#if __CUDA_ARCH__ >= 900
    cudaTriggerProgrammaticLaunchCompletion();
#endif
    int i = blockIdx.x * blockDim.x + threadIdx.x;
    if (i >= N_EDGES) return;
    int src = __ldg(ei + i);
    int dst = __ldg(ei + N_EDGES + i);
    int rel = __ldg(et + i);
    unsigned long long mm = __ldg(&g_relmask[src]);
    int slot = __ldg(&g_pairbase[src]) + __popcll(mm & ((1ull << rel) - 1ull));
    int p = atomicAdd(&g_cur[dst], 1);
    g_eidx[p] = slot;
}

// ---------------- W rows: dense per used (rel,src) pair, FFMA2 --------------
// Launched with programmatic stream serialization: overlaps scatter_kernel.
// Reads only relmask/pairbase/basis (complete before scatter starts); never
// calls cudaGridDependencySynchronize (no dependency on scatter's writes).
__global__ void w_kernel(const float* __restrict__ basis, const float* __restrict__ att) {
    __shared__ unsigned long long s_att2[N_REL * NUM_BASES];   // (c,c) packed
    for (int i = threadIdx.x; i < N_REL * NUM_BASES; i += blockDim.x) {
        float c = att[i];
        unsigned long long p;
        asm("mov.b64 %0, {%1, %1};" : "=l"(p) : "f"(c));
        s_att2[i] = p;
    }
    __syncthreads();

    int warp = threadIdx.x >> 5;
    int lane = threadIdx.x & 31;
    int n = blockIdx.x * (blockDim.x >> 5) + warp;
    if (n >= N_ENTITY) return;

    unsigned long long m = g_relmask[n];
    if (m == 0ull) return;

    unsigned long long bas2[NUM_BASES * 2];
#pragma unroll
    for (int b = 0; b < NUM_BASES; b++) {
        ulonglong2 v = *(const ulonglong2*)(basis + ((size_t)b * N_ENTITY + n) * DIM + lane * 4);
        bas2[2 * b] = v.x;
        bas2[2 * b + 1] = v.y;
    }

    uint2* wp = ((uint2*)g_W) + (size_t)g_pairbase[n] * 32 + lane;

    while (m) {
        int r = __ffsll((long long)m) - 1;
        m &= m - 1;
        unsigned long long a01 = 0ull, a23 = 0ull;
#pragma unroll
        for (int b = 0; b < NUM_BASES; b++) {
            unsigned long long c2 = s_att2[r * NUM_BASES + b];
            asm("fma.rn.f32x2 %0, %1, %2, %0;" : "+l"(a01) : "l"(bas2[2 * b]), "l"(c2));
            asm("fma.rn.f32x2 %0, %1, %2, %0;" : "+l"(a23) : "l"(bas2[2 * b + 1]), "l"(c2));
        }
        float x, y, z, w;
        asm("mov.b64 {%0, %1}, %2;" : "=f"(x), "=f"(y) : "l"(a01));
        asm("mov.b64 {%0, %1}, %2;" : "=f"(z), "=f"(w) : "l"(a23));
        __half2 h01 = __floats2half2_rn(x, y);
        __half2 h23 = __floats2half2_rn(z, w);
        *wp = make_uint2(*(unsigned*)&h01, *(unsigned*)&h23);
        wp += 32;
    }
}

// ---------------- segment aggregation: one warp per dst ---------------------
__device__ __forceinline__ void acc_row(float4& a, int slot, int lane) {
    uint2 pk = __ldg(((const uint2*)g_W) + (size_t)slot * 32 + lane);
    float2 f01 = __half22float2(*(__half2*)&pk.x);
    float2 f23 = __half22float2(*(__half2*)&pk.y);
    a.x += f01.x; a.y += f01.y; a.z += f23.x; a.w += f23.y;
}

__global__ void agg_kernel(const float* __restrict__ root, const float* __restrict__ bias) {
    int dst = blockIdx.x * (blockDim.x >> 5) + (threadIdx.x >> 5);
    if (dst >= N_ENTITY) return;
    int lane = threadIdx.x & 31;

    float4 acc = ((const float4*)root)[(size_t)dst * 32 + lane];
    float4 bb = ((const float4*)bias)[lane];
    acc.x += bb.x; acc.y += bb.y; acc.z += bb.z; acc.w += bb.w;

    int i = __ldg(&g_off[dst]);
    int end = __ldg(&g_off[dst + 1]);

    for (; i + 8 <= end; i += 8) {
        int e0 = __ldg(&g_eidx[i]);
        int e1 = __ldg(&g_eidx[i + 1]);
        int e2 = __ldg(&g_eidx[i + 2]);
        int e3 = __ldg(&g_eidx[i + 3]);
        int e4 = __ldg(&g_eidx[i + 4]);
        int e5 = __ldg(&g_eidx[i + 5]);
        int e6 = __ldg(&g_eidx[i + 6]);
        int e7 = __ldg(&g_eidx[i + 7]);
        acc_row(acc, e0, lane); acc_row(acc, e1, lane);
        acc_row(acc, e2, lane); acc_row(acc, e3, lane);
        acc_row(acc, e4, lane); acc_row(acc, e5, lane);
        acc_row(acc, e6, lane); acc_row(acc, e7, lane);
    }
    for (; i + 4 <= end; i += 4) {
        int e0 = __ldg(&g_eidx[i]);
        int e1 = __ldg(&g_eidx[i + 1]);
        int e2 = __ldg(&g_eidx[i + 2]);
        int e3 = __ldg(&g_eidx[i + 3]);
        acc_row(acc, e0, lane); acc_row(acc, e1, lane);
        acc_row(acc, e2, lane); acc_row(acc, e3, lane);
    }
    for (; i < end; i++) acc_row(acc, __ldg(&g_eidx[i]), lane);

    ((float4*)g_nodes)[(size_t)dst * 32 + lane] = acc;
}

// ---------------- attention pooling over seed sets --------------------------
__global__ void pool_kernel(const int* __restrict__ seed_idx,
                            const void* __restrict__ seed_mask,
                            const float* __restrict__ attn_a,
                            const float* __restrict__ attn_b) {
    int b = blockIdx.x;
    int tid = threadIdx.x;
    int lane = tid & 31;
    int warp = tid >> 5;

    __shared__ float s_h[MAX_SEED][DIM];
    __shared__ float s_e[MAX_SEED];
    __shared__ float s_attn[MAX_SEED];
    __shared__ int   s_idx[MAX_SEED];
    __shared__ unsigned char s_mask[MAX_SEED];

    if (tid < MAX_SEED) {
        s_idx[tid] = seed_idx[b * MAX_SEED + tid];
        int mk;
        if (g_mask_is_int32)
            mk = (((const int*)seed_mask)[b * MAX_SEED + tid] != 0);
        else
            mk = (((const unsigned char*)seed_mask)[b * MAX_SEED + tid] != 0);
        s_mask[tid] = (unsigned char)mk;
    }
    __syncthreads();

    for (int l = 0; l < MAX_SEED; l++)
        s_h[l][tid] = g_nodes[(size_t)s_idx[l] * DIM + tid];
    __syncthreads();

#pragma unroll
    for (int i = 0; i < 8; i++) {
        int l = warp * 8 + i;
        float part = 0.f;
#pragma unroll
        for (int jj = 0; jj < 4; jj++) {
            int j = lane + 32 * jj;
            float m = 0.f;
#pragma unroll 8
            for (int k = 0; k < DIM; k++)
                m += s_h[l][k] * __ldg(attn_a + (size_t)k * DIM + j);
            part += tanhf(m) * __ldg(attn_b + j);
        }
#pragma unroll
        for (int o = 16; o > 0; o >>= 1) part += __shfl_xor_sync(0xffffffffu, part, o);
        if (lane == 0) s_e[l] = part;
    }
    __syncthreads();

    if (warp == 0) {
        float e = s_mask[lane] ? s_e[lane] : -INFINITY;
        float mx = e;
#pragma unroll
        for (int o = 16; o > 0; o >>= 1) mx = fmaxf(mx, __shfl_xor_sync(0xffffffffu, mx, o));
        float p = s_mask[lane] ? __expf(e - mx) : 0.f;
        float sm = p;
#pragma unroll
        for (int o = 16; o > 0; o >>= 1) sm += __shfl_xor_sync(0xffffffffu, sm, o);
        s_attn[lane] = p / sm;
    }
    __syncthreads();

    float u = 0.f;
#pragma unroll
    for (int l = 0; l < MAX_SEED; l++) u += s_attn[l] * s_h[l][tid];
    g_u[b * DIM + tid] = u;
}

// ---------------- scores = u @ nodes^T + output_bias (FFMA2) ----------------
#define TN 64
#define UPAD (BATCH + 4)
#define NPAD (TN + 4)
__global__ void scores_kernel(const float* __restrict__ output_bias,
                              float* __restrict__ out) {
    extern __shared__ float smem[];
    float* s_uT = smem;                    // [DIM][UPAD]
    float* s_nT = smem + DIM * UPAD;       // [DIM][NPAD]

    int tid = threadIdx.x;
    int n0 = blockIdx.x * TN;

    for (int i = tid; i < BATCH * DIM; i += 256) {
        int bb = i >> 7, d = i & 127;
        s_uT[d * UPAD + bb] = g_u[i];
    }
    for (int i = tid; i < TN * DIM; i += 256) {
        int nn = i >> 7, d = i & 127;
        int n = n0 + nn;
        s_nT[d * NPAD + nn] = (n < N_ENTITY) ? g_nodes[(size_t)n * DIM + d] : 0.f;
    }
    __syncthreads();

    int tb = tid >> 4;    // 4 batch rows each
    int tn = tid & 15;    // 4 nodes each
    unsigned long long acc2[4][2];
#pragma unroll
    for (int ii = 0; ii < 4; ii++) { acc2[ii][0] = 0ull; acc2[ii][1] = 0ull; }

#pragma unroll 4
    for (int k = 0; k < DIM; k++) {
        float4 ua = *(const float4*)&s_uT[k * UPAD + 4 * tb];
        ulonglong2 np = *(const ulonglong2*)&s_nT[k * NPAD + 4 * tn];  // (n0,n1),(n2,n3)
        unsigned long long u0, u1, u2, u3;
        asm("mov.b64 %0, {%1, %1};" : "=l"(u0) : "f"(ua.x));
        asm("mov.b64 %0, {%1, %1};" : "=l"(u1) : "f"(ua.y));
        asm("mov.b64 %0, {%1, %1};" : "=l"(u2) : "f"(ua.z));
        asm("mov.b64 %0, {%1, %1};" : "=l"(u3) : "f"(ua.w));
        asm("fma.rn.f32x2 %0, %1, %2, %0;" : "+l"(acc2[0][0]) : "l"(np.x), "l"(u0));
        asm("fma.rn.f32x2 %0, %1, %2, %0;" : "+l"(acc2[0][1]) : "l"(np.y), "l"(u0));
        asm("fma.rn.f32x2 %0, %1, %2, %0;" : "+l"(acc2[1][0]) : "l"(np.x), "l"(u1));
        asm("fma.rn.f32x2 %0, %1, %2, %0;" : "+l"(acc2[1][1]) : "l"(np.y), "l"(u1));
        asm("fma.rn.f32x2 %0, %1, %2, %0;" : "+l"(acc2[2][0]) : "l"(np.x), "l"(u2));
        asm("fma.rn.f32x2 %0, %1, %2, %0;" : "+l"(acc2[2][1]) : "l"(np.y), "l"(u2));
        asm("fma.rn.f32x2 %0, %1, %2, %0;" : "+l"(acc2[3][0]) : "l"(np.x), "l"(u3));
        asm("fma.rn.f32x2 %0, %1, %2, %0;" : "+l"(acc2[3][1]) : "l"(np.y), "l"(u3));
    }

    float acc[4][4];
#pragma unroll
    for (int ii = 0; ii < 4; ii++) {
        asm("mov.b64 {%0, %1}, %2;" : "=f"(acc[ii][0]), "=f"(acc[ii][1]) : "l"(acc2[ii][0]));
        asm("mov.b64 {%0, %1}, %2;" : "=f"(acc[ii][2]), "=f"(acc[ii][3]) : "l"(acc2[ii][1]));
    }

#pragma unroll
    for (int ii = 0; ii < 4; ii++) {
        int bb = 4 * tb + ii;
#pragma unroll
        for (int jj = 0; jj < 4; jj++) {
            int n = n0 + 4 * tn + jj;
            if (n < N_ENTITY)
                out[(size_t)bb * N_ENTITY + n] = acc[ii][jj] + output_bias[n];
        }
    }
}

// ---------------- segmented logsumexp: grid (BATCH, LSE_SEG), float4 --------
__global__ void lse_part_kernel(const float* __restrict__ scores) {
    int b = blockIdx.x;
    int s = blockIdx.y;
    int tid = threadIdx.x;
    const float4* row = (const float4*)(scores + (size_t)b * N_ENTITY + s * SEG_LEN);
    const int n4 = SEG_LEN / 4;   // 1341
    __shared__ float s_red[256];

    float mx = -1e30f;
    for (int i = tid; i < n4; i += 256) {
        float4 v = row[i];
        mx = fmaxf(mx, fmaxf(fmaxf(v.x, v.y), fmaxf(v.z, v.w)));
    }
    s_red[tid] = mx;
    __syncthreads();
    for (int o = 128; o > 0; o >>= 1) {
        if (tid < o) s_red[tid] = fmaxf(s_red[tid], s_red[tid + o]);
        __syncthreads();
    }
    float rmax = s_red[0];
    __syncthreads();

    float sum = 0.f;
    for (int i = tid; i < n4; i += 256) {
        float4 v = row[i];
        sum += __expf(v.x - rmax) + __expf(v.y - rmax) + __expf(v.z - rmax) + __expf(v.w - rmax);
    }
    s_red[tid] = sum;
    __syncthreads();
    for (int o = 128; o > 0; o >>= 1) {
        if (tid < o) s_red[tid] += s_red[tid + o];
        __syncthreads();
    }
    if (tid == 0) {
        g_pmax[b * LSE_SEG + s] = rmax;
        g_psum[b * LSE_SEG + s] = s_red[0];
    }
}

// merge partials + CE mean; one block of BATCH threads
__global__ void lse_final_kernel(const float* __restrict__ scores,
                                 const int* __restrict__ labels,
                                 float* __restrict__ out) {
    __shared__ float s[BATCH];
    int t = threadIdx.x;   // = batch row
    float M = -1e30f;
#pragma unroll
    for (int j = 0; j < LSE_SEG; j++) M = fmaxf(M, g_pmax[t * LSE_SEG + j]);
    float S = 0.f;
#pragma unroll
    for (int j = 0; j < LSE_SEG; j++)
        S += g_psum[t * LSE_SEG + j] * __expf(g_pmax[t * LSE_SEG + j] - M);
    s[t] = (logf(S) + M) - scores[(size_t)t * N_ENTITY + labels[t]];
    __syncthreads();
    for (int o = 32; o > 0; o >>= 1) {
        if (t < o) s[t] += s[t + o];
        __syncthreads();
    }
    if (t == 0) out[(size_t)BATCH * N_ENTITY] = s[0] / (float)BATCH;
}

// ---------------- launch ----------------------------------------------------
extern "C" void kernel_launch(void* const* d_in, const int* in_sizes, int n_in,
                              void* d_out, int out_size) {
    const float* basis       = (const float*)d_in[0];
    const float* att         = (const float*)d_in[1];
    const float* root        = (const float*)d_in[2];
    const float* rgcn_bias   = (const float*)d_in[3];
    const float* attn_a      = (const float*)d_in[4];
    const float* attn_b      = (const float*)d_in[5];
    const float* output_bias = (const float*)d_in[6];
    const int*   edge_index  = (const int*)d_in[7];
    const int*   edge_type   = (const int*)d_in[8];
    const int*   seed_idx    = (const int*)d_in[9];
    const void*  seed_mask   = d_in[10];
    const int*   labels      = (const int*)d_in[11];
    float* out = (float*)d_out;

    const int scores_smem = (int)((DIM * UPAD + DIM * NPAD) * sizeof(float));   // 69632
    static int smem_set = 0;
    if (!smem_set) {
        cudaFuncSetAttribute(scores_kernel, cudaFuncAttributeMaxDynamicSharedMemorySize,
                             scores_smem);
        smem_set = 1;
    }

    zero_aux_kernel<<<(N_ENTITY + 255) / 256 + 1, 256>>>((const unsigned char*)seed_mask);
    edge_pass1_kernel<<<(N_EDGES + 255) / 256, 256>>>(edge_index, edge_type);
    scanA_kernel<<<SCAN_NBLK, SCAN_T>>>();
    scanC_kernel<<<SCAN_NBLK, SCAN_T>>>();
    scatter_kernel<<<(N_EDGES + 255) / 256, 256>>>(edge_index, edge_type);

    // w_kernel overlaps scatter via programmatic dependent launch (PDL):
    // scatter triggers launch-completion immediately; w reads nothing scatter writes.
    {
        cudaLaunchConfig_t cfg = {};
        cfg.gridDim = dim3((N_ENTITY + 7) / 8, 1, 1);
        cfg.blockDim = dim3(256, 1, 1);
        cfg.dynamicSmemBytes = 0;
        cfg.stream = 0;
        cudaLaunchAttribute attr[1];
        attr[0].id = cudaLaunchAttributeProgrammaticStreamSerialization;
        attr[0].val.programmaticStreamSerializationAllowed = 1;
        cfg.attrs = attr;
        cfg.numAttrs = 1;
        cudaLaunchKernelEx(&cfg, w_kernel, basis, att);
    }

    agg_kernel<<<(N_ENTITY + 7) / 8, 256>>>(root, rgcn_bias);
    pool_kernel<<<BATCH, 128>>>(seed_idx, seed_mask, attn_a, attn_b);
    scores_kernel<<<(N_ENTITY + TN - 1) / TN, 256, scores_smem>>>(output_bias, out);
    lse_part_kernel<<<dim3(BATCH, LSE_SEG), 256>>>(out);
    lse_final_kernel<<<1, BATCH>>>(out, labels, out);
}

// round 17
// speedup vs baseline: 1.0998x; 1.0036x over previous
#include <cuda_runtime.h>
#include <cuda_fp16.h>
#include <cstdint>
#include <math.h>

#define N_ENTITY 64368
#define N_REL 40
#define DIM 128
#define NUM_BASES 8
#define N_EDGES 1200000
#define BATCH 64
#define MAX_SEED 32

#define SCAN_T 1024
#define SCAN_NBLK 63          // 63*1024 = 64512 >= N_ENTITY
#define LSE_SEG 12            // 64368 / 12 = 5364, divisible by 4 (float4-aligned)
#define SEG_LEN (N_ENTITY / LSE_SEG)

#if defined(__CUDA_ARCH__) && __CUDA_ARCH__ >= 900
#define GRID_SYNC() cudaGridDependencySynchronize()
#define GRID_TRIGGER() cudaTriggerProgrammaticLaunchCompletion()
#else
#define GRID_SYNC()
#define GRID_TRIGGER()
#endif

// ---------------- device scratch (static: no allocations allowed) ----------
__device__ __half g_W[(size_t)N_EDGES * DIM];            // 307 MB compact fp16 rows
__device__ float  g_nodes[(size_t)N_ENTITY * DIM];       // 33 MB
__device__ float  g_u[BATCH * DIM];
__device__ int    g_mask_is_int32;
__device__ unsigned long long g_relmask[N_ENTITY];       // bit r set if (r,src) used
__device__ int    g_cnt[N_ENTITY];
__device__ unsigned long long g_scantmp[N_ENTITY];       // packed block-local excl scan
__device__ int    g_off[N_ENTITY + 1];
__device__ int    g_cur[N_ENTITY];
__device__ int    g_pairbase[N_ENTITY];                  // excl prefix of popc(relmask)
__device__ unsigned long long g_blocksum[SCAN_NBLK];
__device__ int    g_eidx[N_EDGES];                       // W slot index, grouped by dst
__device__ float  g_pmax[BATCH * LSE_SEG];
__device__ float  g_psum[BATCH * LSE_SEG];

// ---------------- host helper: PDL launch (sync-first secondaries) ----------
template <typename... Args>
static void launch_pdl(void (*kernel)(Args...), dim3 grid, dim3 block, size_t smem,
                       Args... args) {
    cudaLaunchConfig_t cfg = {};
    cfg.gridDim = grid;
    cfg.blockDim = block;
    cfg.dynamicSmemBytes = smem;
    cfg.stream = 0;
    cudaLaunchAttribute attr[1];
    attr[0].id = cudaLaunchAttributeProgrammaticStreamSerialization;
    attr[0].val.programmaticStreamSerializationAllowed = 1;
    cfg.attrs = attr;
    cfg.numAttrs = 1;
    cudaLaunchKernelEx(&cfg, kernel, args...);
}

// ---------------- zero relmask + dst counts; last block detects mask dtype --
__global__ void zero_aux_kernel(const unsigned char* mask) {
    if (blockIdx.x == gridDim.x - 1) {
        __shared__ int s_flag;
        if (threadIdx.x == 0) s_flag = 0;
        __syncthreads();
        for (int i = threadIdx.x; i < BATCH * MAX_SEED; i += blockDim.x) {
            if ((i & 3) != 0 && mask[i] != 0) atomicOr(&s_flag, 1);
        }
        __syncthreads();
        if (threadIdx.x == 0) g_mask_is_int32 = (s_flag == 0) ? 1 : 0;
        return;
    }
    int i = blockIdx.x * blockDim.x + threadIdx.x;
    if (i < N_ENTITY) {
        g_relmask[i] = 0ull;
        g_cnt[i] = 0;
    }
}

// ---------------- build per-src used-relation bitmask + dst histogram -------
__global__ void edge_pass1_kernel(const int* __restrict__ ei, const int* __restrict__ et) {
    int i = blockIdx.x * blockDim.x + threadIdx.x;
    if (i >= N_EDGES) return;
    int src = __ldg(ei + i);
    int dst = __ldg(ei + N_EDGES + i);
    int rel = __ldg(et + i);
    atomicOr(&g_relmask[src], 1ull << rel);
    atomicAdd(&g_cnt[dst], 1);
}

// ---------------- packed dual scan: low32 = dst counts, high32 = pair counts
__global__ void scanA_kernel() {
    __shared__ unsigned long long s[SCAN_T];
    int t = threadIdx.x;
    int idx = blockIdx.x * SCAN_T + t;
    unsigned long long v = 0ull;
    if (idx < N_ENTITY)
        v = (unsigned long long)g_cnt[idx]
          | ((unsigned long long)__popcll(g_relmask[idx]) << 32);
    s[t] = v;
    __syncthreads();
    for (int o = 1; o < SCAN_T; o <<= 1) {
        unsigned long long x = (t >= o) ? s[t - o] : 0ull;
        __syncthreads();
        s[t] += x;
        __syncthreads();
    }
    if (idx < N_ENTITY) g_scantmp[idx] = s[t] - v;   // block-local exclusive
    if (t == SCAN_T - 1) g_blocksum[blockIdx.x] = s[t];
}

__global__ void scanC_kernel() {
    __shared__ unsigned long long s[64];
    int t = threadIdx.x;
    if (t < 64) s[t] = (t < SCAN_NBLK) ? g_blocksum[t] : 0ull;
    __syncthreads();
    for (int o = 1; o < 64; o <<= 1) {
        unsigned long long x = (t >= o && t < 64) ? s[t - o] : 0ull;
        __syncthreads();
        if (t < 64) s[t] += x;
        __syncthreads();
    }
    unsigned long long base = (blockIdx.x == 0) ? 0ull : s[blockIdx.x - 1];
    int idx = blockIdx.x * SCAN_T + t;
    if (idx < N_ENTITY) {
        unsigned long long v = g_scantmp[idx] + base;
        int off = (int)(v & 0xffffffffull);
        g_off[idx] = off;
        g_cur[idx] = off;
        g_pairbase[idx] = (int)(v >> 32);
    }
    if (idx == 0) g_off[N_ENTITY] = N_EDGES;
}

// ---------------- scatter: edge -> dst bucket, payload = compact W slot -----
// Triggers programmatic launch completion FIRST: the following w_kernel (PDL)
// is fully independent of everything this kernel writes.
__global__ void scatter_kernel(const int* __restrict__ ei, const int* __restrict__ et) {
    GRID_TRIGGER();
    int i = blockIdx.x * blockDim.x + threadIdx.x;
    if (i >= N_EDGES) return;
    int src = __ldg(ei + i);
    int dst = __ldg(ei + N_EDGES + i);
    int rel = __ldg(et + i);
    unsigned long long mm = __ldg(&g_relmask[src]);
    int slot = __ldg(&g_pairbase[src]) + __popcll(mm & ((1ull << rel) - 1ull));
    int p = atomicAdd(&g_cur[dst], 1);
    g_eidx[p] = slot;
}

// ---------------- W rows: dense per used (rel,src) pair, FFMA2 --------------
// PDL secondary of scatter; reads only relmask/pairbase/basis (complete before
// scatter starts) -> NO grid sync, overlaps scatter fully.
__global__ void w_kernel(const float* __restrict__ basis, const float* __restrict__ att) {
    __shared__ unsigned long long s_att2[N_REL * NUM_BASES];   // (c,c) packed
    for (int i = threadIdx.x; i < N_REL * NUM_BASES; i += blockDim.x) {
        float c = att[i];
        unsigned long long p;
        asm("mov.b64 %0, {%1, %1};" : "=l"(p) : "f"(c));
        s_att2[i] = p;
    }
    __syncthreads();

    int warp = threadIdx.x >> 5;
    int lane = threadIdx.x & 31;
    int n = blockIdx.x * (blockDim.x >> 5) + warp;
    if (n >= N_ENTITY) return;

    unsigned long long m = g_relmask[n];
    if (m == 0ull) return;

    unsigned long long bas2[NUM_BASES * 2];
#pragma unroll
    for (int b = 0; b < NUM_BASES; b++) {
        ulonglong2 v = *(const ulonglong2*)(basis + ((size_t)b * N_ENTITY + n) * DIM + lane * 4);
        bas2[2 * b] = v.x;
        bas2[2 * b + 1] = v.y;
    }

    uint2* wp = ((uint2*)g_W) + (size_t)g_pairbase[n] * 32 + lane;

    while (m) {
        int r = __ffsll((long long)m) - 1;
        m &= m - 1;
        unsigned long long a01 = 0ull, a23 = 0ull;
#pragma unroll
        for (int b = 0; b < NUM_BASES; b++) {
            unsigned long long c2 = s_att2[r * NUM_BASES + b];
            asm("fma.rn.f32x2 %0, %1, %2, %0;" : "+l"(a01) : "l"(bas2[2 * b]), "l"(c2));
            asm("fma.rn.f32x2 %0, %1, %2, %0;" : "+l"(a23) : "l"(bas2[2 * b + 1]), "l"(c2));
        }
        float x, y, z, w;
        asm("mov.b64 {%0, %1}, %2;" : "=f"(x), "=f"(y) : "l"(a01));
        asm("mov.b64 {%0, %1}, %2;" : "=f"(z), "=f"(w) : "l"(a23));
        __half2 h01 = __floats2half2_rn(x, y);
        __half2 h23 = __floats2half2_rn(z, w);
        *wp = make_uint2(*(unsigned*)&h01, *(unsigned*)&h23);
        wp += 32;
    }
}

// ---------------- segment aggregation: one warp per dst ---------------------
// PLAIN launch: waits for all prior stream work (incl. overlapped scatter).
__device__ __forceinline__ void acc_row(float4& a, int slot, int lane) {
    uint2 pk = __ldg(((const uint2*)g_W) + (size_t)slot * 32 + lane);
    float2 f01 = __half22float2(*(__half2*)&pk.x);
    float2 f23 = __half22float2(*(__half2*)&pk.y);
    a.x += f01.x; a.y += f01.y; a.z += f23.x; a.w += f23.y;
}

__global__ void agg_kernel(const float* __restrict__ root, const float* __restrict__ bias) {
    int dst = blockIdx.x * (blockDim.x >> 5) + (threadIdx.x >> 5);
    if (dst >= N_ENTITY) return;
    int lane = threadIdx.x & 31;

    float4 acc = ((const float4*)root)[(size_t)dst * 32 + lane];
    float4 bb = ((const float4*)bias)[lane];
    acc.x += bb.x; acc.y += bb.y; acc.z += bb.z; acc.w += bb.w;

    int i = __ldg(&g_off[dst]);
    int end = __ldg(&g_off[dst + 1]);

    for (; i + 8 <= end; i += 8) {
        int e0 = __ldg(&g_eidx[i]);
        int e1 = __ldg(&g_eidx[i + 1]);
        int e2 = __ldg(&g_eidx[i + 2]);
        int e3 = __ldg(&g_eidx[i + 3]);
        int e4 = __ldg(&g_eidx[i + 4]);
        int e5 = __ldg(&g_eidx[i + 5]);
        int e6 = __ldg(&g_eidx[i + 6]);
        int e7 = __ldg(&g_eidx[i + 7]);
        acc_row(acc, e0, lane); acc_row(acc, e1, lane);
        acc_row(acc, e2, lane); acc_row(acc, e3, lane);
        acc_row(acc, e4, lane); acc_row(acc, e5, lane);
        acc_row(acc, e6, lane); acc_row(acc, e7, lane);
    }
    for (; i + 4 <= end; i += 4) {
        int e0 = __ldg(&g_eidx[i]);
        int e1 = __ldg(&g_eidx[i + 1]);
        int e2 = __ldg(&g_eidx[i + 2]);
        int e3 = __ldg(&g_eidx[i + 3]);
        acc_row(acc, e0, lane); acc_row(acc, e1, lane);
        acc_row(acc, e2, lane); acc_row(acc, e3, lane);
    }
    for (; i < end; i++) acc_row(acc, __ldg(&g_eidx[i]), lane);

    ((float4*)g_nodes)[(size_t)dst * 32 + lane] = acc;
}

// ---------------- attention pooling over seed sets (PDL, sync-first) --------
__global__ void pool_kernel(const int* __restrict__ seed_idx,
                            const void* __restrict__ seed_mask,
                            const float* __restrict__ attn_a,
                            const float* __restrict__ attn_b) {
    GRID_SYNC();
    int b = blockIdx.x;
    int tid = threadIdx.x;
    int lane = tid & 31;
    int warp = tid >> 5;

    __shared__ float s_h[MAX_SEED][DIM];
    __shared__ float s_e[MAX_SEED];
    __shared__ float s_attn[MAX_SEED];
    __shared__ int   s_idx[MAX_SEED];
    __shared__ unsigned char s_mask[MAX_SEED];

    if (tid < MAX_SEED) {
        s_idx[tid] = seed_idx[b * MAX_SEED + tid];
        int mk;
        if (g_mask_is_int32)
            mk = (((const int*)seed_mask)[b * MAX_SEED + tid] != 0);
        else
            mk = (((const unsigned char*)seed_mask)[b * MAX_SEED + tid] != 0);
        s_mask[tid] = (unsigned char)mk;
    }
    __syncthreads();

    for (int l = 0; l < MAX_SEED; l++)
        s_h[l][tid] = g_nodes[(size_t)s_idx[l] * DIM + tid];
    __syncthreads();

#pragma unroll
    for (int i = 0; i < 8; i++) {
        int l = warp * 8 + i;
        float part = 0.f;
#pragma unroll
        for (int jj = 0; jj < 4; jj++) {
            int j = lane + 32 * jj;
            float m = 0.f;
#pragma unroll 8
            for (int k = 0; k < DIM; k++)
                m += s_h[l][k] * __ldg(attn_a + (size_t)k * DIM + j);
            part += tanhf(m) * __ldg(attn_b + j);
        }
#pragma unroll
        for (int o = 16; o > 0; o >>= 1) part += __shfl_xor_sync(0xffffffffu, part, o);
        if (lane == 0) s_e[l] = part;
    }
    __syncthreads();

    if (warp == 0) {
        float e = s_mask[lane] ? s_e[lane] : -INFINITY;
        float mx = e;
#pragma unroll
        for (int o = 16; o > 0; o >>= 1) mx = fmaxf(mx, __shfl_xor_sync(0xffffffffu, mx, o));
        float p = s_mask[lane] ? __expf(e - mx) : 0.f;
        float sm = p;
#pragma unroll
        for (int o = 16; o > 0; o >>= 1) sm += __shfl_xor_sync(0xffffffffu, sm, o);
        s_attn[lane] = p / sm;
    }
    __syncthreads();

    float u = 0.f;
#pragma unroll
    for (int l = 0; l < MAX_SEED; l++) u += s_attn[l] * s_h[l][tid];
    g_u[b * DIM + tid] = u;
}

// ---------------- scores = u @ nodes^T + output_bias (FFMA2, PDL) -----------
#define TN 64
#define UPAD (BATCH + 4)
#define NPAD (TN + 4)
__global__ void scores_kernel(const float* __restrict__ output_bias,
                              float* __restrict__ out) {
    GRID_SYNC();
    extern __shared__ float smem[];
    float* s_uT = smem;                    // [DIM][UPAD]
    float* s_nT = smem + DIM * UPAD;       // [DIM][NPAD]

    int tid = threadIdx.x;
    int n0 = blockIdx.x * TN;

    for (int i = tid; i < BATCH * DIM; i += 256) {
        int bb = i >> 7, d = i & 127;
        s_uT[d * UPAD + bb] = g_u[i];
    }
    for (int i = tid; i < TN * DIM; i += 256) {
        int nn = i >> 7, d = i & 127;
        int n = n0 + nn;
        s_nT[d * NPAD + nn] = (n < N_ENTITY) ? g_nodes[(size_t)n * DIM + d] : 0.f;
    }
    __syncthreads();

    int tb = tid >> 4;    // 4 batch rows each
    int tn = tid & 15;    // 4 nodes each
    unsigned long long acc2[4][2];
#pragma unroll
    for (int ii = 0; ii < 4; ii++) { acc2[ii][0] = 0ull; acc2[ii][1] = 0ull; }

#pragma unroll 4
    for (int k = 0; k < DIM; k++) {
        float4 ua = *(const float4*)&s_uT[k * UPAD + 4 * tb];
        ulonglong2 np = *(const ulonglong2*)&s_nT[k * NPAD + 4 * tn];  // (n0,n1),(n2,n3)
        unsigned long long u0, u1, u2, u3;
        asm("mov.b64 %0, {%1, %1};" : "=l"(u0) : "f"(ua.x));
        asm("mov.b64 %0, {%1, %1};" : "=l"(u1) : "f"(ua.y));
        asm("mov.b64 %0, {%1, %1};" : "=l"(u2) : "f"(ua.z));
        asm("mov.b64 %0, {%1, %1};" : "=l"(u3) : "f"(ua.w));
        asm("fma.rn.f32x2 %0, %1, %2, %0;" : "+l"(acc2[0][0]) : "l"(np.x), "l"(u0));
        asm("fma.rn.f32x2 %0, %1, %2, %0;" : "+l"(acc2[0][1]) : "l"(np.y), "l"(u0));
        asm("fma.rn.f32x2 %0, %1, %2, %0;" : "+l"(acc2[1][0]) : "l"(np.x), "l"(u1));
        asm("fma.rn.f32x2 %0, %1, %2, %0;" : "+l"(acc2[1][1]) : "l"(np.y), "l"(u1));
        asm("fma.rn.f32x2 %0, %1, %2, %0;" : "+l"(acc2[2][0]) : "l"(np.x), "l"(u2));
        asm("fma.rn.f32x2 %0, %1, %2, %0;" : "+l"(acc2[2][1]) : "l"(np.y), "l"(u2));
        asm("fma.rn.f32x2 %0, %1, %2, %0;" : "+l"(acc2[3][0]) : "l"(np.x), "l"(u3));
        asm("fma.rn.f32x2 %0, %1, %2, %0;" : "+l"(acc2[3][1]) : "l"(np.y), "l"(u3));
    }

    float acc[4][4];
#pragma unroll
    for (int ii = 0; ii < 4; ii++) {
        asm("mov.b64 {%0, %1}, %2;" : "=f"(acc[ii][0]), "=f"(acc[ii][1]) : "l"(acc2[ii][0]));
        asm("mov.b64 {%0, %1}, %2;" : "=f"(acc[ii][2]), "=f"(acc[ii][3]) : "l"(acc2[ii][1]));
    }

#pragma unroll
    for (int ii = 0; ii < 4; ii++) {
        int bb = 4 * tb + ii;
#pragma unroll
        for (int jj = 0; jj < 4; jj++) {
            int n = n0 + 4 * tn + jj;
            if (n < N_ENTITY)
                out[(size_t)bb * N_ENTITY + n] = acc[ii][jj] + output_bias[n];
        }
    }
}

// ---------------- segmented logsumexp: grid (BATCH, LSE_SEG), float4, PDL ---
__global__ void lse_part_kernel(const float* __restrict__ scores) {
    GRID_SYNC();
    int b = blockIdx.x;
    int s = blockIdx.y;
    int tid = threadIdx.x;
    const float4* row = (const float4*)(scores + (size_t)b * N_ENTITY + s * SEG_LEN);
    const int n4 = SEG_LEN / 4;   // 1341
    __shared__ float s_red[256];

    float mx = -1e30f;
    for (int i = tid; i < n4; i += 256) {
        float4 v = row[i];
        mx = fmaxf(mx, fmaxf(fmaxf(v.x, v.y), fmaxf(v.z, v.w)));
    }
    s_red[tid] = mx;
    __syncthreads();
    for (int o = 128; o > 0; o >>= 1) {
        if (tid < o) s_red[tid] = fmaxf(s_red[tid], s_red[tid + o]);
        __syncthreads();
    }
    float rmax = s_red[0];
    __syncthreads();

    float sum = 0.f;
    for (int i = tid; i < n4; i += 256) {
        float4 v = row[i];
        sum += __expf(v.x - rmax) + __expf(v.y - rmax) + __expf(v.z - rmax) + __expf(v.w - rmax);
    }
    s_red[tid] = sum;
    __syncthreads();
    for (int o = 128; o > 0; o >>= 1) {
        if (tid < o) s_red[tid] += s_red[tid + o];
        __syncthreads();
    }
    if (tid == 0) {
        g_pmax[b * LSE_SEG + s] = rmax;
        g_psum[b * LSE_SEG + s] = s_red[0];
    }
}

// merge partials + CE mean; one block of BATCH threads (PDL)
__global__ void lse_final_kernel(const float* __restrict__ scores,
                                 const int* __restrict__ labels,
                                 float* __restrict__ out) {
    GRID_SYNC();
    __shared__ float s[BATCH];
    int t = threadIdx.x;   // = batch row
    float M = -1e30f;
#pragma unroll
    for (int j = 0; j < LSE_SEG; j++) M = fmaxf(M, g_pmax[t * LSE_SEG + j]);
    float S = 0.f;
#pragma unroll
    for (int j = 0; j < LSE_SEG; j++)
        S += g_psum[t * LSE_SEG + j] * __expf(g_pmax[t * LSE_SEG + j] - M);
    s[t] = (logf(S) + M) - scores[(size_t)t * N_ENTITY + labels[t]];
    __syncthreads();
    for (int o = 32; o > 0; o >>= 1) {
        if (t < o) s[t] += s[t + o];
        __syncthreads();
    }
    if (t == 0) out[(size_t)BATCH * N_ENTITY] = s[0] / (float)BATCH;
}

// ---------------- launch ----------------------------------------------------
extern "C" void kernel_launch(void* const* d_in, const int* in_sizes, int n_in,
                              void* d_out, int out_size) {
    const float* basis       = (const float*)d_in[0];
    const float* att         = (const float*)d_in[1];
    const float* root        = (const float*)d_in[2];
    const float* rgcn_bias   = (const float*)d_in[3];
    const float* attn_a      = (const float*)d_in[4];
    const float* attn_b      = (const float*)d_in[5];
    const float* output_bias = (const float*)d_in[6];
    const int*   edge_index  = (const int*)d_in[7];
    const int*   edge_type   = (const int*)d_in[8];
    const int*   seed_idx    = (const int*)d_in[9];
    const void*  seed_mask   = d_in[10];
    const int*   labels      = (const int*)d_in[11];
    float* out = (float*)d_out;

    const size_t scores_smem = (DIM * UPAD + DIM * NPAD) * sizeof(float);   // 69632
    static int smem_set = 0;
    if (!smem_set) {
        cudaFuncSetAttribute(scores_kernel, cudaFuncAttributeMaxDynamicSharedMemorySize,
                             (int)scores_smem);
        smem_set = 1;
    }

    // pre-RGCN chain: plain launches (R15 configuration, known-good)
    zero_aux_kernel<<<(N_ENTITY + 255) / 256 + 1, 256>>>((const unsigned char*)seed_mask);
    edge_pass1_kernel<<<(N_EDGES + 255) / 256, 256>>>(edge_index, edge_type);
    scanA_kernel<<<SCAN_NBLK, SCAN_T>>>();
    scanC_kernel<<<SCAN_NBLK, SCAN_T>>>();
    scatter_kernel<<<(N_EDGES + 255) / 256, 256>>>(edge_index, edge_type);

    // w_kernel: PDL secondary of scatter (early trigger) -> full overlap
    launch_pdl(w_kernel, dim3((N_ENTITY + 7) / 8), dim3(256), 0, basis, att);

    // agg: PLAIN launch (waits for all prior work incl. overlapped scatter)
    agg_kernel<<<(N_ENTITY + 7) / 8, 256>>>(root, rgcn_bias);

    // tail chain: sync-first PDL to hide dispatch gaps
    launch_pdl(pool_kernel, dim3(BATCH), dim3(128), 0,
               seed_idx, seed_mask, attn_a, attn_b);
    launch_pdl(scores_kernel, dim3((N_ENTITY + TN - 1) / TN), dim3(256), scores_smem,
               (const float*)output_bias, out);
    launch_pdl(lse_part_kernel, dim3(BATCH, LSE_SEG), dim3(256), 0, (const float*)out);
    launch_pdl(lse_final_kernel, dim3(1), dim3(BATCH), 0,
               (const float*)out, labels, out);
}